// round 1
// baseline (speedup 1.0000x reference)
#include <cuda_runtime.h>
#include <math.h>

#define T_TOK   8192
#define CIN     768
#define HID     3072
#define NEXP    8
#define DLOW    192
#define FEATROWS (NEXP * DLOW)          /* 1536 */
#define MAIN_SIZE (8 * 768 * 1024)      /* 6291456 */
#define BATCH_STRIDE (CIN * 1024)       /* 786432 */

/* ---------------- scratch (static device globals; no allocation) ------- */
__device__ float g_hT[(size_t)HID * T_TOK];        /* [3072, 8192] hidden, token-contig */
__device__ float g_featsT[(size_t)FEATROWS * T_TOK]; /* [1536, 8192] */
__device__ float g_probsT[NEXP * T_TOK];
__device__ int   g_cnt[NEXP];
__device__ int   g_btok[NEXP * T_TOK];
__device__ float g_bwt[NEXP * T_TOK];

__device__ __forceinline__ float gelu_exact(float v) {
    return 0.5f * v * (1.0f + erff(v * 0.7071067811865475f));
}

/* ---------------- zero the bucket counters ----------------------------- */
__global__ void zero_cnt_kernel() {
    if (threadIdx.x < NEXP) g_cnt[threadIdx.x] = 0;
}

/* ---------------- unified tiled fp32 GEMM ------------------------------
 * Computes C[m, t] = sum_k A[m, k] * B(k, t)   (A row-major [M, K] weights)
 * MODE 0: B = x (native layout), out = g_hT,     epilogue gelu(acc + b1)
 * MODE 1: B = g_hT,              out = d_out,    epilogue x + acc + b2
 * MODE 2: B = x,                 out = g_featsT, epilogue raw
 * Tile 128x128x8, 256 threads, 8x8 per thread.
 */
template <int MODE>
__global__ __launch_bounds__(256)
void gemm_kernel(const float* __restrict__ A,
                 const float* __restrict__ Bx,      /* x for MODE 0/2 */
                 const float* __restrict__ bias,
                 const float* __restrict__ xres,    /* residual for MODE 1 */
                 float* __restrict__ outp,          /* d_out for MODE 1 */
                 int K)
{
    __shared__ float As[8][128];
    __shared__ float Bs[8][128];

    const int m0 = blockIdx.x * 128;
    const int n0 = blockIdx.y * 128;
    const int tid = threadIdx.x;

    const int bb  = n0 >> 10;       /* batch index (tile never crosses batch) */
    const int nl0 = n0 & 1023;

    const float* Bp;
    int ldb;
    if (MODE == 1) { Bp = g_hT + n0; ldb = T_TOK; }
    else           { Bp = Bx + bb * BATCH_STRIDE + nl0; ldb = 1024; }

    const int arow = tid >> 1, acol = (tid & 1) * 4;
    const int brow = tid >> 5, bcol = (tid & 31) * 4;
    const float* Aptr = A + (size_t)(m0 + arow) * K + acol;
    const float* Bptr = Bp + (size_t)brow * ldb + bcol;

    float acc[8][8];
#pragma unroll
    for (int i = 0; i < 8; i++)
#pragma unroll
        for (int j = 0; j < 8; j++) acc[i][j] = 0.f;

    const int tm = (tid >> 4) << 3;
    const int tn = (tid & 15) << 3;

    for (int k0 = 0; k0 < K; k0 += 8) {
        float4 av = *(const float4*)(Aptr + k0);
        float4 bv = *(const float4*)(Bptr + (size_t)k0 * ldb);
        As[acol + 0][arow] = av.x;
        As[acol + 1][arow] = av.y;
        As[acol + 2][arow] = av.z;
        As[acol + 3][arow] = av.w;
        *(float4*)&Bs[brow][bcol] = bv;
        __syncthreads();

#pragma unroll
        for (int k = 0; k < 8; k++) {
            float ar[8], br[8];
#pragma unroll
            for (int i = 0; i < 8; i++) ar[i] = As[k][tm + i];
#pragma unroll
            for (int j = 0; j < 8; j++) br[j] = Bs[k][tn + j];
#pragma unroll
            for (int i = 0; i < 8; i++)
#pragma unroll
                for (int j = 0; j < 8; j++) acc[i][j] += ar[i] * br[j];
        }
        __syncthreads();
    }

#pragma unroll
    for (int i = 0; i < 8; i++) {
        const int m = m0 + tm + i;
        const float bi = (MODE == 2) ? 0.f : bias[m];
        if (MODE == 0) {
            float* o = g_hT + (size_t)m * T_TOK + n0 + tn;
#pragma unroll
            for (int j = 0; j < 8; j++) o[j] = gelu_exact(acc[i][j] + bi);
        } else if (MODE == 1) {
            const size_t base = (size_t)bb * BATCH_STRIDE + (size_t)m * 1024 + nl0 + tn;
#pragma unroll
            for (int j = 0; j < 8; j++) outp[base + j] = xres[base + j] + acc[i][j] + bi;
        } else {
            float* o = g_featsT + (size_t)m * T_TOK + n0 + tn;
#pragma unroll
            for (int j = 0; j < 8; j++) o[j] = acc[i][j];
        }
    }
}

/* ---------------- router: logits, softmax, top-2, bucket push ---------- */
__global__ __launch_bounds__(256)
void router_kernel(const float* __restrict__ rw_g)
{
    __shared__ float rw[DLOW];
    const int tid = threadIdx.x;
    if (tid < DLOW) rw[tid] = rw_g[tid];
    __syncthreads();

    const int t = blockIdx.x * 256 + tid;

    float logit[NEXP];
#pragma unroll
    for (int e = 0; e < NEXP; e++) {
        const float* fp = g_featsT + (size_t)(e * DLOW) * T_TOK + t;
        float a0 = 0.f, a1 = 0.f;
        for (int d = 0; d < DLOW; d += 2) {
            a0 += fp[(size_t)d * T_TOK] * rw[d];
            a1 += fp[(size_t)(d + 1) * T_TOK] * rw[d + 1];
        }
        logit[e] = a0 + a1;
    }

    float mx = logit[0];
#pragma unroll
    for (int e = 1; e < NEXP; e++) mx = fmaxf(mx, logit[e]);
    float p[NEXP], s = 0.f;
#pragma unroll
    for (int e = 0; e < NEXP; e++) { p[e] = expf(logit[e] - mx); s += p[e]; }
    const float inv = 1.f / s;
#pragma unroll
    for (int e = 0; e < NEXP; e++) {
        p[e] *= inv;
        g_probsT[e * T_TOK + t] = p[e];
    }

    /* top-2, ties -> lower index (matches lax.top_k) */
    int i1 = 0;
#pragma unroll
    for (int e = 1; e < NEXP; e++) if (p[e] > p[i1]) i1 = e;
    int i2 = (i1 == 0) ? 1 : 0;
#pragma unroll
    for (int e = 0; e < NEXP; e++) if (e != i1 && p[e] > p[i2]) i2 = e;

    const float wsum = p[i1] + p[i2];
    int pos = atomicAdd(&g_cnt[i1], 1);
    g_btok[i1 * T_TOK + pos] = t;
    g_bwt [i1 * T_TOK + pos] = p[i1] / wsum;
    pos = atomicAdd(&g_cnt[i2], 1);
    g_btok[i2 * T_TOK + pos] = t;
    g_bwt [i2 * T_TOK + pos] = p[i2] / wsum;
}

/* ---------------- per-expert gathered GEMM + atomic epilogue -----------
 * For expert e: out[m, t] += w * sum_d gelu(feats[t, e, d]) * w_up[e, d, m]
 * A[m, k] = w_up[e, k, m] (contiguous in m), B gathered from g_featsT.
 */
__global__ __launch_bounds__(256)
void expert_gemm_kernel(const float* __restrict__ w_up, float* __restrict__ out)
{
    const int e   = blockIdx.z;
    const int n_e = g_cnt[e];
    const int n0  = blockIdx.y * 128;
    if (n0 >= n_e) return;
    const int m0  = blockIdx.x * 128;
    const int tid = threadIdx.x;

    __shared__ float As[8][128];
    __shared__ float Bs[8][128];
    __shared__ int   stok[128];
    __shared__ float swt[128];

    if (tid < 128) {
        const int j = n0 + tid;
        stok[tid] = (j < n_e) ? g_btok[e * T_TOK + j] : -1;
        swt [tid] = (j < n_e) ? g_bwt [e * T_TOK + j] : 0.f;
    }
    __syncthreads();

    const float* Ae = w_up + (size_t)e * DLOW * CIN;   /* [d, m] */
    const int lk = tid >> 5;
    const int lm4 = (tid & 31) * 4;

    float acc[8][8];
#pragma unroll
    for (int i = 0; i < 8; i++)
#pragma unroll
        for (int j = 0; j < 8; j++) acc[i][j] = 0.f;

    const int tm = (tid >> 4) << 3;
    const int tn = (tid & 15) << 3;

    for (int k0 = 0; k0 < DLOW; k0 += 8) {
        float4 av = *(const float4*)(Ae + (size_t)(k0 + lk) * CIN + m0 + lm4);
        *(float4*)&As[lk][lm4] = av;

        const float* frow = g_featsT + (size_t)(e * DLOW + k0 + lk) * T_TOK;
#pragma unroll
        for (int u = 0; u < 4; u++) {
            const int j = lm4 + u;
            const int tk = stok[j];
            Bs[lk][j] = (tk >= 0) ? gelu_exact(frow[tk]) : 0.f;
        }
        __syncthreads();

#pragma unroll
        for (int k = 0; k < 8; k++) {
            float ar[8], br[8];
#pragma unroll
            for (int i = 0; i < 8; i++) ar[i] = As[k][tm + i];
#pragma unroll
            for (int j = 0; j < 8; j++) br[j] = Bs[k][tn + j];
#pragma unroll
            for (int i = 0; i < 8; i++)
#pragma unroll
                for (int j = 0; j < 8; j++) acc[i][j] += ar[i] * br[j];
        }
        __syncthreads();
    }

#pragma unroll
    for (int j = 0; j < 8; j++) {
        const int jj = tn + j;
        const int tk = stok[jj];
        if (tk < 0) continue;
        const float w = swt[jj];
        const size_t tb = (size_t)(tk >> 10) * BATCH_STRIDE + (tk & 1023);
#pragma unroll
        for (int i = 0; i < 8; i++) {
            const int m = m0 + tm + i;
            atomicAdd(&out[tb + (size_t)m * 1024], acc[i][j] * w);
        }
    }
}

/* ---------------- aux load-balance loss (deterministic reduction) ------ */
__global__ __launch_bounds__(256)
void aux_kernel(float* __restrict__ out, int out_size)
{
    __shared__ float red[NEXP][256];
    const int tid = threadIdx.x;
    for (int e = 0; e < NEXP; e++) {
        float s = 0.f;
        for (int t = tid; t < T_TOK; t += 256) s += g_probsT[e * T_TOK + t];
        red[e][tid] = s;
    }
    __syncthreads();
    for (int off = 128; off; off >>= 1) {
        if (tid < off)
            for (int e = 0; e < NEXP; e++) red[e][tid] += red[e][tid + off];
        __syncthreads();
    }
    if (tid == 0) {
        float aux = 0.f;
        for (int e = 0; e < NEXP; e++) {
            const float meanp = red[e][0] / (float)T_TOK;
            const float meanl = (float)g_cnt[e] / (float)T_TOK;
            aux += meanp * meanl;
        }
        aux *= (float)NEXP;
        for (int i = MAIN_SIZE; i < out_size; i++) out[i] = aux;
    }
}

/* ---------------- launch --------------------------------------------- */
extern "C" void kernel_launch(void* const* d_in, const int* in_sizes, int n_in,
                              void* d_out, int out_size)
{
    const float* x        = (const float*)d_in[0];
    const float* w1       = (const float*)d_in[1];
    const float* b1       = (const float*)d_in[2];
    const float* w2       = (const float*)d_in[3];
    const float* b2       = (const float*)d_in[4];
    const float* w_down   = (const float*)d_in[5];
    const float* router_w = (const float*)d_in[6];
    const float* w_up     = (const float*)d_in[7];
    float* out = (float*)d_out;

    zero_cnt_kernel<<<1, 32>>>();

    /* router features first (keeps feats hot in L2 for the router pass) */
    gemm_kernel<2><<<dim3(FEATROWS / 128, T_TOK / 128), 256>>>(
        w_down, x, nullptr, nullptr, nullptr, CIN);
    router_kernel<<<T_TOK / 256, 256>>>(router_w);

    /* shared expert */
    gemm_kernel<0><<<dim3(HID / 128, T_TOK / 128), 256>>>(
        w1, x, b1, nullptr, nullptr, CIN);
    gemm_kernel<1><<<dim3(CIN / 128, T_TOK / 128), 256>>>(
        w2, nullptr, b2, x, out, HID);

    /* AoE expert contribution (atomicAdd into out) */
    expert_gemm_kernel<<<dim3(CIN / 128, T_TOK / 128, NEXP), 256>>>(w_up, out);

    /* aux loss appended after the main tensor */
    aux_kernel<<<1, 256>>>(out, out_size);
}

// round 3
// speedup vs baseline: 2.1166x; 2.1166x over previous
#include <cuda_runtime.h>
#include <math.h>
#include <stdint.h>

#define T_TOK   8192
#define CIN     768
#define HID     3072
#define NEXP    8
#define DLOW    192
#define FEATW   1536
#define MAIN_SIZE (8 * 768 * 1024)
#define BSTR    (CIN * 1024)

/* ---------------- scratch ---------------- */
__device__ float g_xT[(size_t)T_TOK * CIN];      /* [t][k] */
__device__ float g_H[(size_t)T_TOK * HID];       /* [t][h] */
__device__ float g_feats[(size_t)T_TOK * FEATW]; /* [t][e*192+d] */
__device__ float g_C[CIN * NEXP];
__device__ float g_probsT[NEXP * T_TOK];
__device__ int   g_cnt[NEXP];
__device__ int   g_btok[NEXP * T_TOK];
__device__ float g_bwt[NEXP * T_TOK];

__device__ __forceinline__ float gelu_exact(float v) {
    return 0.5f * v * (1.0f + erff(v * 0.7071067811865475f));
}
__device__ __forceinline__ uint32_t smem_u32(const void* p) {
    uint32_t a;
    asm("{ .reg .u64 t; cvta.to.shared.u64 t, %1; cvt.u32.u64 %0, t; }" : "=r"(a) : "l"(p));
    return a;
}
__device__ __forceinline__ float to_tf32(float v) {
    float o;
    asm("cvt.rna.tf32.f32 %0, %1;" : "=f"(o) : "f"(v));
    return o;
}
__device__ __forceinline__ void ldsm4(uint32_t& r0, uint32_t& r1, uint32_t& r2,
                                      uint32_t& r3, uint32_t addr) {
    asm volatile("ldmatrix.sync.aligned.m8n8.x4.shared.b16 {%0,%1,%2,%3}, [%4];"
                 : "=r"(r0), "=r"(r1), "=r"(r2), "=r"(r3) : "r"(addr));
}
__device__ __forceinline__ void mma8(float* c, const uint32_t* a, uint32_t b0, uint32_t b1) {
    asm volatile("mma.sync.aligned.m16n8k8.row.col.f32.tf32.tf32.f32 "
                 "{%0,%1,%2,%3}, {%4,%5,%6,%7}, {%8,%9}, {%0,%1,%2,%3};"
                 : "+f"(c[0]), "+f"(c[1]), "+f"(c[2]), "+f"(c[3])
                 : "r"(a[0]), "r"(a[1]), "r"(a[2]), "r"(a[3]), "r"(b0), "r"(b1));
}

/* ---------------- small kernels ---------------- */
__global__ void zero_cnt_kernel() { if (threadIdx.x < NEXP) g_cnt[threadIdx.x] = 0; }

__global__ void transpose_x_kernel(const float* __restrict__ x) {
    __shared__ float tb[32][33];
    const int b = blockIdx.z, p0 = blockIdx.x * 32, k0 = blockIdx.y * 32;
    const int tx = threadIdx.x, ty0 = threadIdx.y;
#pragma unroll
    for (int i = 0; i < 4; i++) {
        const int ty = ty0 + i * 8;
        tb[ty][tx] = x[(size_t)b * BSTR + (size_t)(k0 + ty) * 1024 + p0 + tx];
    }
    __syncthreads();
#pragma unroll
    for (int i = 0; i < 4; i++) {
        const int ty = ty0 + i * 8;
        g_xT[(size_t)(b * 1024 + p0 + ty) * CIN + k0 + tx] = tb[tx][ty];
    }
}

__global__ void precompC_kernel(const float* __restrict__ wd, const float* __restrict__ r) {
    __shared__ float rs[DLOW];
    const int e = blockIdx.x, k = threadIdx.x;
    if (k < DLOW) rs[k] = r[k];
    __syncthreads();
    double s = 0.0;
    for (int d = 0; d < DLOW; d++)
        s += (double)wd[(size_t)(e * DLOW + d) * CIN + k] * (double)rs[d];
    g_C[k * NEXP + e] = (float)s;
}

__global__ __launch_bounds__(256)
void router_kernel(const float* __restrict__ x) {
    __shared__ float Cs[CIN * NEXP];
    const int tid = threadIdx.x;
    for (int i = tid; i < CIN * NEXP; i += 256) Cs[i] = g_C[i];
    __syncthreads();

    const int t = blockIdx.x * 256 + tid;
    const float* xp = x + (size_t)(t >> 10) * BSTR + (t & 1023);

    float lg[NEXP];
#pragma unroll
    for (int e = 0; e < NEXP; e++) lg[e] = 0.f;
    for (int k = 0; k < CIN; k++) {
        const float xv = xp[(size_t)k * 1024];
#pragma unroll
        for (int e = 0; e < NEXP; e++) lg[e] += xv * Cs[k * NEXP + e];
    }

    float mx = lg[0];
#pragma unroll
    for (int e = 1; e < NEXP; e++) mx = fmaxf(mx, lg[e]);
    float p[NEXP], s = 0.f;
#pragma unroll
    for (int e = 0; e < NEXP; e++) { p[e] = expf(lg[e] - mx); s += p[e]; }
    const float inv = 1.f / s;
#pragma unroll
    for (int e = 0; e < NEXP; e++) { p[e] *= inv; g_probsT[e * T_TOK + t] = p[e]; }

    int i1 = 0;
#pragma unroll
    for (int e = 1; e < NEXP; e++) if (p[e] > p[i1]) i1 = e;
    int i2 = (i1 == 0) ? 1 : 0;
#pragma unroll
    for (int e = 0; e < NEXP; e++) if (e != i1 && p[e] > p[i2]) i2 = e;

    const float wsum = p[i1] + p[i2];
    int pos = atomicAdd(&g_cnt[i1], 1);
    g_btok[i1 * T_TOK + pos] = t;
    g_bwt [i1 * T_TOK + pos] = p[i1] / wsum;
    pos = atomicAdd(&g_cnt[i2], 1);
    g_btok[i2 * T_TOK + pos] = t;
    g_bwt [i2 * T_TOK + pos] = p[i2] / wsum;
}

/* ---------------- tf32 warp-MMA GEMM ----------------------------------
 * C[m,n] = sum_k Ap[m,k] * Bp[n,k], both operands K-contiguous.
 * MODE 0 (H):    A=g_xT (m=token), B=w1 (n=hid),  g_H[m][n]=gelu(c+b1[n])
 * MODE 2 (FEAT): A=g_xT,           B=w_down,      g_feats[m][n]=c
 * MODE 1 (OUT):  A=W2 (m=cout),    B=g_H (n=tok), out = x + c + b2[m]
 * Block 128x128, BK=16, 256 thr (8 warps as 2x4, warp tile 64x32).
 */
template <int MODE>
__global__ __launch_bounds__(256)
void mma_gemm(const float* __restrict__ Aparam, const float* __restrict__ Bparam,
              const float* __restrict__ bias, const float* __restrict__ xres,
              float* __restrict__ outp, int K)
{
    __shared__ float As[2][128][20];
    __shared__ float Bs[2][128][20];

    const int tid  = threadIdx.x;
    const int lane = tid & 31, warp = tid >> 5;
    const int wm = warp >> 2, wn = warp & 3;
    const int m0 = blockIdx.x * 128, n0 = blockIdx.y * 128;

    const float* Abase = (MODE == 1) ? Aparam : g_xT;
    const float* Bbase = (MODE == 1) ? g_H : Bparam;

    const int grow = tid >> 1, gseg = (tid & 1) * 8;
    const float* pA = Abase + (size_t)(m0 + grow) * K + gseg;
    const float* pB = Bbase + (size_t)(n0 + grow) * K + gseg;

    float c[4][4][4];
#pragma unroll
    for (int i = 0; i < 4; i++)
#pragma unroll
        for (int j = 0; j < 4; j++)
#pragma unroll
            for (int q = 0; q < 4; q++) c[i][j][q] = 0.f;

    float4 ra0, ra1, rb0, rb1;

#define CVT_ST(dst, v0, v1) do {                                              \
        float* d_ = (dst);                                                    \
        d_[0]=to_tf32((v0).x); d_[1]=to_tf32((v0).y);                         \
        d_[2]=to_tf32((v0).z); d_[3]=to_tf32((v0).w);                         \
        d_[4]=to_tf32((v1).x); d_[5]=to_tf32((v1).y);                         \
        d_[6]=to_tf32((v1).z); d_[7]=to_tf32((v1).w);                         \
    } while (0)

    ra0 = *(const float4*)(pA);     ra1 = *(const float4*)(pA + 4);
    rb0 = *(const float4*)(pB);     rb1 = *(const float4*)(pB + 4);
    CVT_ST(&As[0][grow][gseg], ra0, ra1);
    CVT_ST(&Bs[0][grow][gseg], rb0, rb1);
    __syncthreads();

    const int NT = K / 16;
    const int rsub = (lane & 7) + ((lane >> 3) & 1) * 8;
    const int chalf = ((lane >> 4) & 1) * 4;

    for (int kt = 0; kt < NT; kt++) {
        const int b = kt & 1;
        if (kt + 1 < NT) {
            const float* qA = pA + (size_t)(kt + 1) * 16;
            const float* qB = pB + (size_t)(kt + 1) * 16;
            ra0 = *(const float4*)(qA);     ra1 = *(const float4*)(qA + 4);
            rb0 = *(const float4*)(qB);     rb1 = *(const float4*)(qB + 4);
        }

        const uint32_t abase = smem_u32(&As[b][0][0]);
        const uint32_t bbase = smem_u32(&Bs[b][0][0]);
#pragma unroll
        for (int ks = 0; ks < 2; ks++) {
            const int colf = ks * 8 + chalf;
            uint32_t a[4][4], bf[2][4];
#pragma unroll
            for (int mf = 0; mf < 4; mf++) {
                const int row = wm * 64 + mf * 16 + rsub;
                ldsm4(a[mf][0], a[mf][1], a[mf][2], a[mf][3],
                      abase + (uint32_t)(row * 20 + colf) * 4u);
            }
#pragma unroll
            for (int np = 0; np < 2; np++) {
                const int row = wn * 32 + np * 16 + rsub;
                ldsm4(bf[np][0], bf[np][1], bf[np][2], bf[np][3],
                      bbase + (uint32_t)(row * 20 + colf) * 4u);
            }
#pragma unroll
            for (int mf = 0; mf < 4; mf++)
#pragma unroll
                for (int nf = 0; nf < 4; nf++)
                    mma8(c[mf][nf], a[mf], bf[nf >> 1][nf & 1], bf[nf >> 1][2 + (nf & 1)]);
        }
        __syncthreads();
        if (kt + 1 < NT) {
            CVT_ST(&As[b ^ 1][grow][gseg], ra0, ra1);
            CVT_ST(&Bs[b ^ 1][grow][gseg], rb0, rb1);
            __syncthreads();
        }
    }
#undef CVT_ST

    /* epilogue */
#pragma unroll
    for (int mf = 0; mf < 4; mf++)
#pragma unroll
        for (int nf = 0; nf < 4; nf++)
#pragma unroll
            for (int h = 0; h < 2; h++) {
                const int gm = m0 + wm * 64 + mf * 16 + (lane >> 2) + h * 8;
                const int gn = n0 + wn * 32 + nf * 8 + (lane & 3) * 2;
                float v0 = c[mf][nf][h * 2 + 0];
                float v1 = c[mf][nf][h * 2 + 1];
                if (MODE == 0) {
                    v0 = gelu_exact(v0 + bias[gn]);
                    v1 = gelu_exact(v1 + bias[gn + 1]);
                    *(float2*)&g_H[(size_t)gm * HID + gn] = make_float2(v0, v1);
                } else if (MODE == 2) {
                    *(float2*)&g_feats[(size_t)gm * FEATW + gn] = make_float2(v0, v1);
                } else {
                    const size_t off = (size_t)(gn >> 10) * BSTR + (size_t)gm * 1024 + (gn & 1023);
                    const float2 xr = *(const float2*)&xres[off];
                    const float bv = bias[gm];
                    *(float2*)&outp[off] = make_float2(xr.x + v0 + bv, xr.y + v1 + bv);
                }
            }
}

/* ---------------- per-expert gathered fp32 GEMM + atomic epilogue ------ */
__global__ __launch_bounds__(256)
void expert_gemm_kernel(const float* __restrict__ w_up, float* __restrict__ out)
{
    const int e   = blockIdx.z;
    const int n_e = g_cnt[e];
    const int n0  = blockIdx.y * 128;
    if (n0 >= n_e) return;
    const int m0  = blockIdx.x * 128;
    const int tid = threadIdx.x;

    __shared__ float As[8][128];
    __shared__ float Bs[8][128];
    __shared__ int   stok[128];
    __shared__ float swt[128];

    if (tid < 128) {
        const int j = n0 + tid;
        stok[tid] = (j < n_e) ? g_btok[e * T_TOK + j] : -1;
        swt [tid] = (j < n_e) ? g_bwt [e * T_TOK + j] : 0.f;
    }
    __syncthreads();

    const float* Ae = w_up + (size_t)e * DLOW * CIN;
    const int lk = tid >> 5;
    const int lm4 = (tid & 31) * 4;

    float acc[8][8];
#pragma unroll
    for (int i = 0; i < 8; i++)
#pragma unroll
        for (int j = 0; j < 8; j++) acc[i][j] = 0.f;

    const int tm = (tid >> 4) << 3;
    const int tn = (tid & 15) << 3;

    for (int k0 = 0; k0 < DLOW; k0 += 8) {
        float4 av = *(const float4*)(Ae + (size_t)(k0 + lk) * CIN + m0 + lm4);
        *(float4*)&As[lk][lm4] = av;
#pragma unroll
        for (int u = 0; u < 4; u++) {
            const int j = lm4 + u;
            const int tk = stok[j];
            Bs[lk][j] = (tk >= 0)
                ? gelu_exact(g_feats[(size_t)tk * FEATW + e * DLOW + k0 + lk]) : 0.f;
        }
        __syncthreads();
#pragma unroll
        for (int k = 0; k < 8; k++) {
            float ar[8], br[8];
#pragma unroll
            for (int i = 0; i < 8; i++) ar[i] = As[k][tm + i];
#pragma unroll
            for (int j = 0; j < 8; j++) br[j] = Bs[k][tn + j];
#pragma unroll
            for (int i = 0; i < 8; i++)
#pragma unroll
                for (int j = 0; j < 8; j++) acc[i][j] += ar[i] * br[j];
        }
        __syncthreads();
    }

#pragma unroll
    for (int j = 0; j < 8; j++) {
        const int jj = tn + j;
        const int tk = stok[jj];
        if (tk < 0) continue;
        const float w = swt[jj];
        const size_t tb = (size_t)(tk >> 10) * BSTR + (tk & 1023);
#pragma unroll
        for (int i = 0; i < 8; i++)
            atomicAdd(&out[tb + (size_t)(m0 + tm + i) * 1024], acc[i][j] * w);
    }
}

/* ---------------- aux loss ---------------- */
__global__ __launch_bounds__(256)
void aux_kernel(float* __restrict__ out, int out_size)
{
    __shared__ float red[NEXP][256];
    const int tid = threadIdx.x;
    for (int e = 0; e < NEXP; e++) {
        float s = 0.f;
        for (int t = tid; t < T_TOK; t += 256) s += g_probsT[e * T_TOK + t];
        red[e][tid] = s;
    }
    __syncthreads();
    for (int off = 128; off; off >>= 1) {
        if (tid < off)
            for (int e = 0; e < NEXP; e++) red[e][tid] += red[e][tid + off];
        __syncthreads();
    }
    if (tid == 0) {
        float aux = 0.f;
        for (int e = 0; e < NEXP; e++)
            aux += (red[e][0] / (float)T_TOK) * ((float)g_cnt[e] / (float)T_TOK);
        aux *= (float)NEXP;
        for (int i = MAIN_SIZE; i < out_size; i++) out[i] = aux;
    }
}

/* ---------------- launch ---------------- */
extern "C" void kernel_launch(void* const* d_in, const int* in_sizes, int n_in,
                              void* d_out, int out_size)
{
    const float* x        = (const float*)d_in[0];
    const float* w1       = (const float*)d_in[1];
    const float* b1       = (const float*)d_in[2];
    const float* w2       = (const float*)d_in[3];
    const float* b2       = (const float*)d_in[4];
    const float* w_down   = (const float*)d_in[5];
    const float* router_w = (const float*)d_in[6];
    const float* w_up     = (const float*)d_in[7];
    float* out = (float*)d_out;

    zero_cnt_kernel<<<1, 32>>>();
    transpose_x_kernel<<<dim3(32, 24, 8), dim3(32, 8)>>>(x);
    precompC_kernel<<<NEXP, CIN>>>(w_down, router_w);
    router_kernel<<<T_TOK / 256, 256>>>(x);

    /* feats: m=token(64), n=featrow(12), K=768 */
    mma_gemm<2><<<dim3(64, 12), 256>>>(nullptr, w_down, nullptr, nullptr, nullptr, CIN);
    /* H: m=token(64), n=hid(24), K=768 */
    mma_gemm<0><<<dim3(64, 24), 256>>>(nullptr, w1, b1, nullptr, nullptr, CIN);
    /* OUT: m=cout(6), n=token(64), K=3072 */
    mma_gemm<1><<<dim3(6, 64), 256>>>(w2, nullptr, b2, x, out, HID);

    expert_gemm_kernel<<<dim3(6, 64, NEXP), 256>>>(w_up, out);
    aux_kernel<<<1, 256>>>(out, out_size);
}

// round 4
// speedup vs baseline: 2.5880x; 1.2227x over previous
#include <cuda_runtime.h>
#include <math.h>
#include <stdint.h>

#define T_TOK   8192
#define CIN     768
#define HID     3072
#define NEXP    8
#define DLOW    192
#define FEATW   1536
#define MAIN_SIZE (8 * 768 * 1024)
#define BSTR    (CIN * 1024)

#define BM 128
#define BN 128
#define BK 32
#define ROWF 36                 /* floats per smem row (32 + 4 pad) */
#define STAGE_F ((BM + BN) * ROWF)
#define SMEM_BYTES (3 * STAGE_F * 4)

/* ---------------- scratch ---------------- */
__device__ float g_xT[(size_t)T_TOK * CIN];
__device__ float g_H[(size_t)T_TOK * HID];
__device__ float g_feats[(size_t)T_TOK * FEATW];
__device__ float g_C[CIN * NEXP];
__device__ float g_probsT[NEXP * T_TOK];
__device__ int   g_cnt[NEXP];
__device__ int   g_btok[NEXP * T_TOK];
__device__ float g_bwt[NEXP * T_TOK];

__device__ __forceinline__ float gelu_exact(float v) {
    return 0.5f * v * (1.0f + erff(v * 0.7071067811865475f));
}
__device__ __forceinline__ uint32_t smem_u32(const void* p) {
    uint32_t a;
    asm("{ .reg .u64 t; cvta.to.shared.u64 t, %1; cvt.u32.u64 %0, t; }" : "=r"(a) : "l"(p));
    return a;
}
__device__ __forceinline__ void ldsm4(uint32_t& r0, uint32_t& r1, uint32_t& r2,
                                      uint32_t& r3, uint32_t addr) {
    asm volatile("ldmatrix.sync.aligned.m8n8.x4.shared.b16 {%0,%1,%2,%3}, [%4];"
                 : "=r"(r0), "=r"(r1), "=r"(r2), "=r"(r3) : "r"(addr));
}
__device__ __forceinline__ void mma8(float* c, const uint32_t* a, uint32_t b0, uint32_t b1) {
    asm volatile("mma.sync.aligned.m16n8k8.row.col.f32.tf32.tf32.f32 "
                 "{%0,%1,%2,%3}, {%4,%5,%6,%7}, {%8,%9}, {%0,%1,%2,%3};"
                 : "+f"(c[0]), "+f"(c[1]), "+f"(c[2]), "+f"(c[3])
                 : "r"(a[0]), "r"(a[1]), "r"(a[2]), "r"(a[3]), "r"(b0), "r"(b1));
}
__device__ __forceinline__ void cp16(uint32_t dst, const void* src) {
    asm volatile("cp.async.cg.shared.global [%0], [%1], 16;" :: "r"(dst), "l"(src) : "memory");
}
__device__ __forceinline__ void cp_commit() {
    asm volatile("cp.async.commit_group;" ::: "memory");
}
__device__ __forceinline__ void cp_wait1() {
    asm volatile("cp.async.wait_group 1;" ::: "memory");
}
__device__ __forceinline__ void cp_wait0() {
    asm volatile("cp.async.wait_group 0;" ::: "memory");
}

/* ---------------- small kernels ---------------- */
__global__ void zero_cnt_kernel() { if (threadIdx.x < NEXP) g_cnt[threadIdx.x] = 0; }

__global__ void transpose_x_kernel(const float* __restrict__ x) {
    __shared__ float tb[32][33];
    const int b = blockIdx.z, p0 = blockIdx.x * 32, k0 = blockIdx.y * 32;
    const int tx = threadIdx.x, ty0 = threadIdx.y;
#pragma unroll
    for (int i = 0; i < 4; i++) {
        const int ty = ty0 + i * 8;
        tb[ty][tx] = x[(size_t)b * BSTR + (size_t)(k0 + ty) * 1024 + p0 + tx];
    }
    __syncthreads();
#pragma unroll
    for (int i = 0; i < 4; i++) {
        const int ty = ty0 + i * 8;
        g_xT[(size_t)(b * 1024 + p0 + ty) * CIN + k0 + tx] = tb[tx][ty];
    }
}

__global__ void precompC_kernel(const float* __restrict__ wd, const float* __restrict__ r) {
    __shared__ float rs[DLOW];
    const int e = blockIdx.x, k = threadIdx.x;
    if (k < DLOW) rs[k] = r[k];
    __syncthreads();
    double s = 0.0;
    for (int d = 0; d < DLOW; d++)
        s += (double)wd[(size_t)(e * DLOW + d) * CIN + k] * (double)rs[d];
    g_C[k * NEXP + e] = (float)s;
}

/* router v2: 4 threads per token split K, shuffle-reduce; grid = 128 */
__global__ __launch_bounds__(256)
void router_kernel() {
    __shared__ float Cs[CIN * NEXP];
    const int tid = threadIdx.x;
    for (int i = tid; i < CIN * NEXP; i += 256)
        Cs[i] = g_C[i];
    __syncthreads();

    const int sub = tid & 3;
    const int t = blockIdx.x * 64 + (tid >> 2);
    const float* xp = g_xT + (size_t)t * CIN + sub * 192;

    float lg[NEXP];
#pragma unroll
    for (int e = 0; e < NEXP; e++) lg[e] = 0.f;
    const float* cbase = Cs + sub * 192 * NEXP;
    for (int k = 0; k < 192; k += 4) {
        const float4 xv = *(const float4*)(xp + k);
        const float* cp = cbase + k * NEXP;
#pragma unroll
        for (int e = 0; e < NEXP; e++)
            lg[e] += xv.x * cp[e] + xv.y * cp[NEXP + e]
                   + xv.z * cp[2 * NEXP + e] + xv.w * cp[3 * NEXP + e];
    }
#pragma unroll
    for (int off = 1; off < 4; off <<= 1)
#pragma unroll
        for (int e = 0; e < NEXP; e++)
            lg[e] += __shfl_xor_sync(0xffffffffu, lg[e], off);

    if (sub == 0) {
        float mx = lg[0];
#pragma unroll
        for (int e = 1; e < NEXP; e++) mx = fmaxf(mx, lg[e]);
        float p[NEXP], s = 0.f;
#pragma unroll
        for (int e = 0; e < NEXP; e++) { p[e] = expf(lg[e] - mx); s += p[e]; }
        const float inv = 1.f / s;
#pragma unroll
        for (int e = 0; e < NEXP; e++) { p[e] *= inv; g_probsT[e * T_TOK + t] = p[e]; }

        int i1 = 0;
#pragma unroll
        for (int e = 1; e < NEXP; e++) if (p[e] > p[i1]) i1 = e;
        int i2 = (i1 == 0) ? 1 : 0;
#pragma unroll
        for (int e = 0; e < NEXP; e++) if (e != i1 && p[e] > p[i2]) i2 = e;

        const float wsum = p[i1] + p[i2];
        int pos = atomicAdd(&g_cnt[i1], 1);
        g_btok[i1 * T_TOK + pos] = t;
        g_bwt [i1 * T_TOK + pos] = p[i1] / wsum;
        pos = atomicAdd(&g_cnt[i2], 1);
        g_btok[i2 * T_TOK + pos] = t;
        g_bwt [i2 * T_TOK + pos] = p[i2] / wsum;
    }
}

/* ---------------- tf32 warp-MMA GEMM, cp.async 3-stage -----------------
 * C[m,n] = sum_k A[m,k] * B[n,k], both K-contiguous.
 * MODE 0: A=g_xT(tok), B=w1,   g_H = gelu(c + b1[n])
 * MODE 2: A=g_xT(tok), B=w_down, g_feats = c
 * MODE 1: A=W2(cout),  B=g_H,  out = x + c + b2[m]
 */
template <int MODE>
__global__ __launch_bounds__(256)
void mma_gemm(const float* __restrict__ Aparam, const float* __restrict__ Bparam,
              const float* __restrict__ bias, const float* __restrict__ xres,
              float* __restrict__ outp, int K)
{
    extern __shared__ float smf[];

    const int tid  = threadIdx.x;
    const int lane = tid & 31, warp = tid >> 5;
    const int wm = warp >> 2, wn = warp & 3;
    const int m0 = blockIdx.x * BM, n0 = blockIdx.y * BN;

    const float* Abase = (MODE == 1) ? Aparam : g_xT;
    const float* Bbase = (MODE == 1) ? g_H : Bparam;
    const float* pAg = Abase + (size_t)m0 * K;
    const float* pBg = Bbase + (size_t)n0 * K;

    float c[4][4][4];
#pragma unroll
    for (int i = 0; i < 4; i++)
#pragma unroll
        for (int j = 0; j < 4; j++)
#pragma unroll
            for (int q = 0; q < 4; q++) c[i][j][q] = 0.f;

    /* cp.async stage fill: 1024 A-chunks + 1024 B-chunks of 16B, 4+4 per thread */
#define ISSUE(KT, S) do {                                                     \
        float* as_ = smf + (S) * STAGE_F;                                     \
        float* bs_ = as_ + BM * ROWF;                                         \
        const uint32_t au_ = smem_u32(as_);                                   \
        const uint32_t bu_ = smem_u32(bs_);                                   \
        _Pragma("unroll")                                                     \
        for (int i_ = 0; i_ < 4; i_++) {                                      \
            const int c_ = tid + 256 * i_;                                    \
            const int r_ = c_ >> 3, sg_ = c_ & 7;                             \
            cp16(au_ + (uint32_t)(r_ * ROWF + sg_ * 4) * 4u,                  \
                 pAg + (size_t)r_ * K + (KT) * BK + sg_ * 4);                 \
            cp16(bu_ + (uint32_t)(r_ * ROWF + sg_ * 4) * 4u,                  \
                 pBg + (size_t)r_ * K + (KT) * BK + sg_ * 4);                 \
        }                                                                     \
    } while (0)

    const int NT = K / BK;
    ISSUE(0, 0); cp_commit();
    ISSUE(1, 1); cp_commit();

    const int rsub  = (lane & 7) + ((lane >> 3) & 1) * 8;
    const int chalf = ((lane >> 4) & 1) * 4;

    for (int kt = 0; kt < NT; kt++) {
        if (kt == NT - 1) cp_wait0(); else cp_wait1();
        __syncthreads();
        if (kt + 2 < NT) { ISSUE(kt + 2, (kt + 2) % 3); cp_commit(); }

        const int s = kt % 3;
        const uint32_t abase = smem_u32(smf + s * STAGE_F);
        const uint32_t bbase = abase + BM * ROWF * 4u;
#pragma unroll
        for (int ks = 0; ks < 4; ks++) {
            const int colf = ks * 8 + chalf;
            uint32_t a[4][4], bf[2][4];
#pragma unroll
            for (int mf = 0; mf < 4; mf++) {
                const int row = wm * 64 + mf * 16 + rsub;
                ldsm4(a[mf][0], a[mf][1], a[mf][2], a[mf][3],
                      abase + (uint32_t)(row * ROWF + colf) * 4u);
            }
#pragma unroll
            for (int np = 0; np < 2; np++) {
                const int row = wn * 32 + np * 16 + rsub;
                ldsm4(bf[np][0], bf[np][1], bf[np][2], bf[np][3],
                      bbase + (uint32_t)(row * ROWF + colf) * 4u);
            }
#pragma unroll
            for (int mf = 0; mf < 4; mf++)
#pragma unroll
                for (int nf = 0; nf < 4; nf++)
                    mma8(c[mf][nf], a[mf], bf[nf >> 1][nf & 1], bf[nf >> 1][2 + (nf & 1)]);
        }
        __syncthreads();
    }
#undef ISSUE

    /* epilogue */
#pragma unroll
    for (int mf = 0; mf < 4; mf++)
#pragma unroll
        for (int nf = 0; nf < 4; nf++)
#pragma unroll
            for (int h = 0; h < 2; h++) {
                const int gm = m0 + wm * 64 + mf * 16 + (lane >> 2) + h * 8;
                const int gn = n0 + wn * 32 + nf * 8 + (lane & 3) * 2;
                float v0 = c[mf][nf][h * 2 + 0];
                float v1 = c[mf][nf][h * 2 + 1];
                if (MODE == 0) {
                    v0 = gelu_exact(v0 + bias[gn]);
                    v1 = gelu_exact(v1 + bias[gn + 1]);
                    *(float2*)&g_H[(size_t)gm * HID + gn] = make_float2(v0, v1);
                } else if (MODE == 2) {
                    *(float2*)&g_feats[(size_t)gm * FEATW + gn] = make_float2(v0, v1);
                } else {
                    const size_t off = (size_t)(gn >> 10) * BSTR + (size_t)gm * 1024 + (gn & 1023);
                    const float2 xr = *(const float2*)&xres[off];
                    const float bv = bias[gm];
                    *(float2*)&outp[off] = make_float2(xr.x + v0 + bv, xr.y + v1 + bv);
                }
            }
}

/* ---------------- per-expert gathered fp32 GEMM + atomic epilogue ------ */
__global__ __launch_bounds__(256)
void expert_gemm_kernel(const float* __restrict__ w_up, float* __restrict__ out)
{
    const int e   = blockIdx.z;
    const int n_e = g_cnt[e];
    const int n0  = blockIdx.y * 128;
    if (n0 >= n_e) return;
    const int m0  = blockIdx.x * 128;
    const int tid = threadIdx.x;

    __shared__ float As[8][128];
    __shared__ float Bs[8][128];
    __shared__ int   stok[128];
    __shared__ float swt[128];

    if (tid < 128) {
        const int j = n0 + tid;
        stok[tid] = (j < n_e) ? g_btok[e * T_TOK + j] : -1;
        swt [tid] = (j < n_e) ? g_bwt [e * T_TOK + j] : 0.f;
    }
    __syncthreads();

    const float* Ae = w_up + (size_t)e * DLOW * CIN;
    const int lk = tid >> 5;
    const int lm4 = (tid & 31) * 4;

    float acc[8][8];
#pragma unroll
    for (int i = 0; i < 8; i++)
#pragma unroll
        for (int j = 0; j < 8; j++) acc[i][j] = 0.f;

    const int tm = (tid >> 4) << 3;
    const int tn = (tid & 15) << 3;

    for (int k0 = 0; k0 < DLOW; k0 += 8) {
        float4 av = *(const float4*)(Ae + (size_t)(k0 + lk) * CIN + m0 + lm4);
        *(float4*)&As[lk][lm4] = av;
#pragma unroll
        for (int u = 0; u < 4; u++) {
            const int j = lm4 + u;
            const int tk = stok[j];
            Bs[lk][j] = (tk >= 0)
                ? gelu_exact(g_feats[(size_t)tk * FEATW + e * DLOW + k0 + lk]) : 0.f;
        }
        __syncthreads();
#pragma unroll
        for (int k = 0; k < 8; k++) {
            float ar[8], br[8];
#pragma unroll
            for (int i = 0; i < 8; i++) ar[i] = As[k][tm + i];
#pragma unroll
            for (int j = 0; j < 8; j++) br[j] = Bs[k][tn + j];
#pragma unroll
            for (int i = 0; i < 8; i++)
#pragma unroll
                for (int j = 0; j < 8; j++) acc[i][j] += ar[i] * br[j];
        }
        __syncthreads();
    }

#pragma unroll
    for (int j = 0; j < 8; j++) {
        const int jj = tn + j;
        const int tk = stok[jj];
        if (tk < 0) continue;
        const float w = swt[jj];
        const size_t tb = (size_t)(tk >> 10) * BSTR + (tk & 1023);
#pragma unroll
        for (int i = 0; i < 8; i++)
            atomicAdd(&out[tb + (size_t)(m0 + tm + i) * 1024], acc[i][j] * w);
    }
}

/* ---------------- aux loss ---------------- */
__global__ __launch_bounds__(256)
void aux_kernel(float* __restrict__ out, int out_size)
{
    __shared__ float red[NEXP][256];
    const int tid = threadIdx.x;
    for (int e = 0; e < NEXP; e++) {
        float s = 0.f;
        for (int t = tid; t < T_TOK; t += 256) s += g_probsT[e * T_TOK + t];
        red[e][tid] = s;
    }
    __syncthreads();
    for (int off = 128; off; off >>= 1) {
        if (tid < off)
            for (int e = 0; e < NEXP; e++) red[e][tid] += red[e][tid + off];
        __syncthreads();
    }
    if (tid == 0) {
        float aux = 0.f;
        for (int e = 0; e < NEXP; e++)
            aux += (red[e][0] / (float)T_TOK) * ((float)g_cnt[e] / (float)T_TOK);
        aux *= (float)NEXP;
        for (int i = MAIN_SIZE; i < out_size; i++) out[i] = aux;
    }
}

/* ---------------- launch ---------------- */
extern "C" void kernel_launch(void* const* d_in, const int* in_sizes, int n_in,
                              void* d_out, int out_size)
{
    const float* x        = (const float*)d_in[0];
    const float* w1       = (const float*)d_in[1];
    const float* b1       = (const float*)d_in[2];
    const float* w2       = (const float*)d_in[3];
    const float* b2       = (const float*)d_in[4];
    const float* w_down   = (const float*)d_in[5];
    const float* router_w = (const float*)d_in[6];
    const float* w_up     = (const float*)d_in[7];
    float* out = (float*)d_out;

    cudaFuncSetAttribute(mma_gemm<0>, cudaFuncAttributeMaxDynamicSharedMemorySize, SMEM_BYTES);
    cudaFuncSetAttribute(mma_gemm<1>, cudaFuncAttributeMaxDynamicSharedMemorySize, SMEM_BYTES);
    cudaFuncSetAttribute(mma_gemm<2>, cudaFuncAttributeMaxDynamicSharedMemorySize, SMEM_BYTES);

    zero_cnt_kernel<<<1, 32>>>();
    transpose_x_kernel<<<dim3(32, 24, 8), dim3(32, 8)>>>(x);
    precompC_kernel<<<NEXP, CIN>>>(w_down, router_w);
    router_kernel<<<128, 256>>>();

    mma_gemm<2><<<dim3(64, 12), 256, SMEM_BYTES>>>(nullptr, w_down, nullptr, nullptr, nullptr, CIN);
    mma_gemm<0><<<dim3(64, 24), 256, SMEM_BYTES>>>(nullptr, w1, b1, nullptr, nullptr, CIN);
    mma_gemm<1><<<dim3(6, 64), 256, SMEM_BYTES>>>(w2, nullptr, b2, x, out, HID);

    expert_gemm_kernel<<<dim3(6, 64, NEXP), 256>>>(w_up, out);
    aux_kernel<<<1, 256>>>(out, out_size);
}